// round 15
// baseline (speedup 1.0000x reference)
#include <cuda_runtime.h>
#include <cuda_fp16.h>

#define NB 2048
#define NF 4096
#define NC 8192
#define NT 8
#define NK 1024
#define NS 8
#define MB 16           // batch rows per tile (two fp16 8-row halves per feat)
#define THREADS 1024    // one k per thread
#define HALF_OFF 65536  // byte offset of rows 8-15 half in smem

// 16-bit slot table, layout [s][k][t]: index = (s*NK + k)*NT + t.
// slot = feat | (sign>0 ? 0 : 0x1000).
// smem: half0 = rows 0-7  at (feat*16),
//       half1 = rows 8-15 at (feat*16 + 65536). Same bank group per half.
// Slots within each (k,s) group are shaped (sorted by bank group, rotated
// by k&7) to reduce LDS conflict phases.
__device__ unsigned short g_slot[NS * NK * NT];   // 128 KB

__global__ void prep_kernel(const int* __restrict__ conj_feat,
                            const int* __restrict__ conj_sign,
                            const int* __restrict__ class_conj) {
    int i = blockIdx.x * blockDim.x + threadIdx.x;   // i = s*NK + k (k fast)
    if (i >= NS * NK) return;
    int s = i >> 10;
    int k = i & (NK - 1);
    int c = class_conj[k * NS + s];

    const int4* fp = (const int4*)(conj_feat + (size_t)c * NT);
    const int4* sp = (const int4*)(conj_sign + (size_t)c * NT);
    int4 f0 = fp[0], f1 = fp[1];
    int4 s0 = sp[0], s1 = sp[1];

    unsigned a[8];
    a[0] = (unsigned)f0.x | (s0.x > 0 ? 0u : 0x1000u);
    a[1] = (unsigned)f0.y | (s0.y > 0 ? 0u : 0x1000u);
    a[2] = (unsigned)f0.z | (s0.z > 0 ? 0u : 0x1000u);
    a[3] = (unsigned)f0.w | (s0.w > 0 ? 0u : 0x1000u);
    a[4] = (unsigned)f1.x | (s1.x > 0 ? 0u : 0x1000u);
    a[5] = (unsigned)f1.y | (s1.y > 0 ? 0u : 0x1000u);
    a[6] = (unsigned)f1.z | (s1.z > 0 ? 0u : 0x1000u);
    a[7] = (unsigned)f1.w | (s1.w > 0 ? 0u : 0x1000u);

    // Batcher odd-even sort by bank group (feat & 7); static indices only.
#define CSWP(p, q) do { \
        if ((a[p] & 7u) > (a[q] & 7u)) { unsigned _t = a[p]; a[p] = a[q]; a[q] = _t; } \
    } while (0)
    CSWP(0,1); CSWP(2,3); CSWP(4,5); CSWP(6,7);
    CSWP(0,2); CSWP(1,3); CSWP(4,6); CSWP(5,7);
    CSWP(1,2); CSWP(5,6);
    CSWP(0,4); CSWP(1,5); CSWP(2,6); CSWP(3,7);
    CSWP(2,4); CSWP(3,5);
    CSWP(1,2); CSWP(3,4); CSWP(5,6);
#undef CSWP

    int r = k & 7;                       // rotate by k&7 (stratify per warp)
    #pragma unroll
    for (int st = 0; st < 3; st++) {
        int amt = 1 << st;
        if (r & amt) {
            unsigned tmp[8];
            #pragma unroll
            for (int j = 0; j < 8; j++) tmp[j] = a[(j + amt) & 7];
            #pragma unroll
            for (int j = 0; j < 8; j++) a[j] = tmp[j];
        }
    }

    uint4 w;
    w.x = a[0] | (a[1] << 16);
    w.y = a[2] | (a[3] << 16);
    w.z = a[4] | (a[5] << 16);
    w.w = a[6] | (a[7] << 16);
    ((uint4*)g_slot)[i] = w;
}

static __device__ __forceinline__ unsigned hfma2u(unsigned a, unsigned b, unsigned c) {
    __half2 ha = *reinterpret_cast<__half2*>(&a);
    __half2 hb = *reinterpret_cast<__half2*>(&b);
    __half2 hc = *reinterpret_cast<__half2*>(&c);
    __half2 hr = __hfma2(ha, hb, hc);
    return *reinterpret_cast<unsigned*>(&hr);
}
static __device__ __forceinline__ unsigned hmul2u(unsigned a, unsigned b) {
    __half2 ha = *reinterpret_cast<__half2*>(&a);
    __half2 hb = *reinterpret_cast<__half2*>(&b);
    __half2 hr = __hmul2(ha, hb);
    return *reinterpret_cast<unsigned*>(&hr);
}
static __device__ __forceinline__ unsigned hmax2u(unsigned a, unsigned b) {
    __half2 ha = *reinterpret_cast<__half2*>(&a);
    __half2 hb = *reinterpret_cast<__half2*>(&b);
    __half2 hr = __hmax2(ha, hb);
    return *reinterpret_cast<unsigned*>(&hr);
}
static __device__ __forceinline__ uint4 mulh8(uint4 a, uint4 b) {
    a.x = hmul2u(a.x, b.x); a.y = hmul2u(a.y, b.y);
    a.z = hmul2u(a.z, b.z); a.w = hmul2u(a.w, b.w);
    return a;
}
static __device__ __forceinline__ uint4 maxh8(uint4 a, uint4 b) {
    a.x = hmax2u(a.x, b.x); a.y = hmax2u(a.y, b.y);
    a.z = hmax2u(a.z, b.z); a.w = hmax2u(a.w, b.w);
    return a;
}
static __device__ __forceinline__ unsigned pack2(float a, float b) {
    __half2 h = __floats2half2_rn(a, b);
    return *reinterpret_cast<unsigned*>(&h);
}

// One literal = 16 rows: two LDS.128 (halves at +0 / +HALF_OFF, same addr calc),
// one pair of sign constants, 8 HFMA2. lo/hi returned via refs.
static __device__ __forceinline__ void literal16(const char* sb, unsigned v,
                                                 uint4& lo, uint4& hi) {
    unsigned a = (v & 0xFFFu) << 4;
    uint4 qlo = *(const uint4*)(sb + a);
    uint4 qhi = *(const uint4*)(sb + a + HALF_OFF);
    bool neg = (v & 0x1000u) != 0;
    unsigned m2 = neg ? 0xBC00BC00u : 0x3C003C00u;   // -1 or +1 (half2)
    unsigned c2 = neg ? 0x3C003C00u : 0x00000000u;   //  1 or  0 (half2)
    qlo.x = hfma2u(qlo.x, m2, c2);  qhi.x = hfma2u(qhi.x, m2, c2);
    qlo.y = hfma2u(qlo.y, m2, c2);  qhi.y = hfma2u(qhi.y, m2, c2);
    qlo.z = hfma2u(qlo.z, m2, c2);  qhi.z = hfma2u(qhi.z, m2, c2);
    qlo.w = hfma2u(qlo.w, m2, c2);  qhi.w = hfma2u(qhi.w, m2, c2);
    lo = qlo; hi = qhi;
}

__global__ void __launch_bounds__(THREADS, 1)
dnf_kernel(const float* __restrict__ x, float* __restrict__ out) {
    extern __shared__ unsigned smem_u[];   // 128 KB: two 64 KB halves
    const int b0 = blockIdx.x * MB;

    // Phase A: stage 16 rows. f = tid stride (coalesced LDG per row);
    // both halves stored with 16B lane stride -> conflict-free STS.128.
    uint4* slo = (uint4*)smem_u;                       // rows 0-7
    uint4* shi = (uint4*)((char*)smem_u + HALF_OFF);   // rows 8-15
    for (int f = threadIdx.x; f < NF; f += THREADS) {
        float v[MB];
        #pragma unroll
        for (int r = 0; r < MB; r++)
            v[r] = x[(size_t)(b0 + r) * NF + f];
        uint4 lo, hi;
        lo.x = pack2(v[0], v[1]);    hi.x = pack2(v[8],  v[9]);
        lo.y = pack2(v[2], v[3]);    hi.y = pack2(v[10], v[11]);
        lo.z = pack2(v[4], v[5]);    hi.z = pack2(v[12], v[13]);
        lo.w = pack2(v[6], v[7]);    hi.w = pack2(v[14], v[15]);
        slo[f] = lo;
        shi[f] = hi;
    }
    __syncthreads();

    const char* sb = (const char*)smem_u;
    const int k = threadIdx.x;                       // NK == THREADS
    const uint4* tab = (const uint4*)g_slot + k;     // tab[s*NK]

    uint4 ta = tab[0];
    uint4 tb = tab[NK];
    uint4 mxlo = make_uint4(0u, 0u, 0u, 0u);         // products >= 0
    uint4 mxhi = make_uint4(0u, 0u, 0u, 0u);

    #pragma unroll
    for (int s = 0; s < NS; s++) {
        int spre = s + 2 < NS - 1 ? s + 2 : NS - 1;  // prefetch s+2 (clamped)
        uint4 tn = tab[spre * NK];

        uint4 l0, h0, l1, h1, l2, h2, l3, h3;
        uint4 l4, h4, l5, h5, l6, h6, l7, h7;
        literal16(sb, ta.x & 0xFFFFu, l0, h0);
        literal16(sb, ta.x >> 16,     l1, h1);
        literal16(sb, ta.y & 0xFFFFu, l2, h2);
        literal16(sb, ta.y >> 16,     l3, h3);
        literal16(sb, ta.z & 0xFFFFu, l4, h4);
        literal16(sb, ta.z >> 16,     l5, h5);
        literal16(sb, ta.w & 0xFFFFu, l6, h6);
        literal16(sb, ta.w >> 16,     l7, h7);

        uint4 plo = mulh8(mulh8(mulh8(l0, l1), mulh8(l2, l3)),
                          mulh8(mulh8(l4, l5), mulh8(l6, l7)));
        uint4 phi = mulh8(mulh8(mulh8(h0, h1), mulh8(h2, h3)),
                          mulh8(mulh8(h4, h5), mulh8(h6, h7)));
        mxlo = maxh8(mxlo, plo);
        mxhi = maxh8(mxhi, phi);
        ta = tb;
        tb = tn;
    }

    // Unpack 16 rows and store (coalesced: lanes = consecutive k).
    #pragma unroll
    for (int j = 0; j < 4; j++) {
        unsigned wlo = j == 0 ? mxlo.x : j == 1 ? mxlo.y : j == 2 ? mxlo.z : mxlo.w;
        unsigned whi = j == 0 ? mxhi.x : j == 1 ? mxhi.y : j == 2 ? mxhi.z : mxhi.w;
        float2 rlo = __half22float2(*reinterpret_cast<__half2*>(&wlo));
        float2 rhi = __half22float2(*reinterpret_cast<__half2*>(&whi));
        out[(size_t)(b0 + 2 * j + 0) * NK + k]     = rlo.x;
        out[(size_t)(b0 + 2 * j + 1) * NK + k]     = rlo.y;
        out[(size_t)(b0 + 8 + 2 * j + 0) * NK + k] = rhi.x;
        out[(size_t)(b0 + 8 + 2 * j + 1) * NK + k] = rhi.y;
    }
}

extern "C" void kernel_launch(void* const* d_in, const int* in_sizes, int n_in,
                              void* d_out, int out_size) {
    const float* x  = (const float*)d_in[0];
    const int*   cf = (const int*)d_in[1];
    const int*   cs = (const int*)d_in[2];
    const int*   cc = (const int*)d_in[3];
    float* out = (float*)d_out;

    prep_kernel<<<(NS * NK + 255) / 256, 256>>>(cf, cs, cc);

    size_t smem_bytes = (size_t)NF * MB * sizeof(__half);  // 131072
    cudaFuncSetAttribute(dnf_kernel,
                         cudaFuncAttributeMaxDynamicSharedMemorySize,
                         (int)smem_bytes);
    dnf_kernel<<<NB / MB, THREADS, smem_bytes>>>(x, out);
}